// round 13
// baseline (speedup 1.0000x reference)
#include <cuda_runtime.h>
#include <math.h>
#include <stdint.h>
#include <float.h>

#define NB    2048
#define NC    9605
#define NL    20
#define NCP   9616                    // NC rounded up to 16
#define BDIM  256
#define CCAP  768                     // per-row candidate capacity
#define T1    2.5f                    // ~60 candidates expected for N(0,1)
#define TOTCH ((NB * NC) / 4)         // int4 chunks (exact: NB*NC % 4 == 0)
#define GRIDM 4736
#define SPAN  ((TOTCH + GRIDM - 1) / GRIDM)   // 1039 chunks -> block touches <=2 rows

// Scratch (no allocations allowed)
__device__ __align__(16) unsigned char d_tabs[4][NCP]; // shifted class->group
__device__ int      d_hist[4];
__device__ int      d_actg[NB];       // per-row group-activity bitmask (y)
__device__ int      d_ang[NB];        // per-row group-activity bitmask (y_neg)
__device__ unsigned d_gmax[NB][NL];   // per-row fenc'd group maxima
__device__ int      d_ccnt[NB];       // per-row candidate counts
__device__ float    d_cand[NB][CCAP]; // per-row candidate values
__device__ int      d_rowdone[NB];    // per-row covering-block completion count
__device__ float    d_loss[NB];
__device__ int      d_done2;

// ---------------------------------------------------------------------------
// init + dtype detection fused
// ---------------------------------------------------------------------------
__global__ void __launch_bounds__(256)
initdetect_kernel(const unsigned char* __restrict__ raw) {
    int t0 = blockIdx.x * blockDim.x + threadIdx.x;
    int gs = gridDim.x * blockDim.x;
    if (t0 == 0) {
        d_done2 = 0;
        d_hist[0] = d_hist[1] = d_hist[2] = d_hist[3] = 0;
    }
    for (int i = t0; i < NB; i += gs) {
        d_actg[i] = 0; d_ang[i] = 0; d_ccnt[i] = 0; d_rowdone[i] = 0;
    }
    for (int i = t0; i < NB * NL; i += gs) ((unsigned*)d_gmax)[i] = 0u;
    {
        uint4* p = (uint4*)d_tabs;
        const uint4 ff = make_uint4(0xFFFFFFFFu, 0xFFFFFFFFu,
                                    0xFFFFFFFFu, 0xFFFFFFFFu);
        for (int i = t0; i < (4 * NCP) / 16; i += gs) p[i] = ff;
    }
    // detect: flag nonzero bytes by (offset mod 4) over first NL*NC bytes
    const int total = NL * NC;
    const uint4* r4 = (const uint4*)raw;
    int f0 = 0, f1 = 0, f2 = 0, f3 = 0;
    int nv = total >> 4;
    for (int i = t0; i < nv; i += gs) {
        uint4 w = __ldg(r4 + i);
        unsigned a = w.x | w.y | w.z | w.w;
        f0 |= (a & 0x000000FFu) != 0;
        f1 |= (a & 0x0000FF00u) != 0;
        f2 |= (a & 0x00FF0000u) != 0;
        f3 |= (a & 0xFF000000u) != 0;
    }
    if (blockIdx.x == 0) {
        for (int i = (nv << 4) + threadIdx.x; i < total; i += blockDim.x)
            if (raw[i]) { int m = i & 3;
                f0 |= (m == 0); f1 |= (m == 1); f2 |= (m == 2); f3 |= (m == 3); }
    }
    if (f0) atomicOr(&d_hist[0], 1);
    if (f1) atomicOr(&d_hist[1], 1);
    if (f2) atomicOr(&d_hist[2], 1);
    if (f3) atomicOr(&d_hist[3], 1);
}

__device__ __forceinline__ void tab_set(int c, unsigned char g) {
#pragma unroll
    for (int h = 0; h < 4; ++h)
        if (c >= h) d_tabs[h][c - h] = g;
}

__global__ void __launch_bounds__(256)
build_kernel(const void* __restrict__ maskv) {
    int h0 = d_hist[0], h1 = d_hist[1], h2 = d_hist[2], h3 = d_hist[3];
    int mode;  // 0 = uint8, 1 = int32, 2 = float32
    if (h0 && !h1 && !h2 && !h3)        mode = 1;
    else if (!h0 && !h1 && (h2 || h3))  mode = 2;
    else                                 mode = 0;

    const int total = NL * NC;
    const int gs = gridDim.x * blockDim.x;
    const int t0 = blockIdx.x * blockDim.x + threadIdx.x;

    if (mode != 0) {
        const int4* m4 = (const int4*)maskv;  // int32/float32: !=0 bit test
        int nv = total >> 2;
        for (int i = t0; i < nv; i += gs) {
            int4 w = __ldg(m4 + i);
            int base = i << 2;
#pragma unroll
            for (int u = 0; u < 4; ++u) {
                int bits = (u == 0) ? w.x : (u == 1) ? w.y : (u == 2) ? w.z : w.w;
                if (bits != 0) {
                    int idx = base + u;
                    tab_set(idx % NC, (unsigned char)(idx / NC));
                }
            }
        }
        for (int idx = (nv << 2) + t0; idx < total; idx += gs)
            if (((const int*)maskv)[idx] != 0)
                tab_set(idx % NC, (unsigned char)(idx / NC));
    } else {
        const unsigned char* m8 = (const unsigned char*)maskv;
        for (int idx = t0; idx < total; idx += gs)
            if (m8[idx])
                tab_set(idx % NC, (unsigned char)(idx / NC));
    }
}

__device__ __forceinline__ float sigmoidf_(float v) {
    return 1.0f / (1.0f + expf(-v));
}
__device__ __forceinline__ float rankl(float x1, float x2) {
    float d = x2 - x1 + 0.05f;
    float s = 1.0f / (1.0f + expf(-10.0f * d));
    return (d > 0.0f) ? 2.0f * s : s;
}
__device__ __forceinline__ unsigned fenc(float v) {
    unsigned u = __float_as_uint(v);
    return (u & 0x80000000u) ? ~u : (u | 0x80000000u);
}
__device__ __forceinline__ float fdec(unsigned u) {
    return (u & 0x80000000u) ? __uint_as_float(u ^ 0x80000000u)
                             : __uint_as_float(~u);
}

// number of scan blocks covering row r (consecutive span blocks)
__device__ __forceinline__ int nblk_row(int r) {
    int fc = (r * NC) >> 2;
    int lc = ((r + 1) * NC - 1) >> 2;
    return lc / SPAN - fc / SPAN + 1;
}

// warp-collective per-row finalization: 11th-largest + loss
__device__ void finalize_row(int b, const float* __restrict__ x, int lane) {
    int cnt = *(volatile int*)&d_ccnt[b];
    const float* xr = x + (size_t)b * NC;

    if (cnt < 11 || cnt > CCAP) {
        // bisection fallback (unreachable for the bench distribution)
        float tlo = -3.0e38f, thi = 3.0e38f, thr = T1;
        for (int it = 0; it < 120; ++it) {
            int local = 0;
            for (int c = lane; c < NC; c += 32) local += (__ldg(xr + c) > thr);
#pragma unroll
            for (int o = 16; o > 0; o >>= 1)
                local += __shfl_down_sync(0xffffffffu, local, o);
            int c2 = __shfl_sync(0xffffffffu, local, 0);
            if (c2 > 128)     { tlo = thr; }
            else if (c2 < 11) { thi = thr; }
            else break;
            thr = 0.5f * (tlo + thi);
        }
        if (lane == 0) d_ccnt[b] = 0;
        __syncwarp();
        for (int c = lane; c < NC; c += 32) {
            float v = __ldg(xr + c);
            if (v > thr) {
                int p = atomicAdd(&d_ccnt[b], 1);
                if (p < CCAP) d_cand[b][p] = v;
            }
        }
        __syncwarp();
        cnt = d_ccnt[b];
        if (cnt > CCAP) cnt = CCAP;
    }

    float v11;
    if (cnt <= 128) {
        float v0 = (lane      < cnt) ? d_cand[b][lane]      : -FLT_MAX;
        float v1 = (lane + 32 < cnt) ? d_cand[b][lane + 32] : -FLT_MAX;
        float v2 = (lane + 64 < cnt) ? d_cand[b][lane + 64] : -FLT_MAX;
        float v3 = (lane + 96 < cnt) ? d_cand[b][lane + 96] : -FLT_MAX;
        v11 = -FLT_MAX;
#pragma unroll
        for (int r = 0; r < 11; ++r) {
            float lm = fmaxf(fmaxf(v0, v1), fmaxf(v2, v3));
            float m = lm;
#pragma unroll
            for (int o = 16; o > 0; o >>= 1)
                m = fmaxf(m, __shfl_xor_sync(0xffffffffu, m, o));
            if (r == 10) { v11 = m; break; }
            unsigned ballot = __ballot_sync(0xffffffffu, lm == m);
            int owner = __ffs(ballot) - 1;
            if (lane == owner) {
                if      (v0 == m) v0 = -FLT_MAX;
                else if (v1 == m) v1 = -FLT_MAX;
                else if (v2 == m) v2 = -FLT_MAX;
                else              v3 = -FLT_MAX;
            }
        }
    } else {
        float found = -FLT_MAX;
        for (int i2 = lane; i2 < cnt; i2 += 32) {
            float vi = d_cand[b][i2];
            int rank = 0;
            for (int j = 0; j < cnt; ++j) {
                float vj = d_cand[b][j];
                rank += (vj > vi) || (vj == vi && j < i2);
            }
            if (rank == 10) found = vi;
        }
#pragma unroll
        for (int o = 16; o > 0; o >>= 1)
            found = fmaxf(found, __shfl_xor_sync(0xffffffffu, found, o));
        v11 = found;
    }

    if (lane == 0) {
        const float thres = fmaxf(sigmoidf_(v11), 0.5f);
        const int act = d_actg[b];
        const int an  = d_ang[b];

        float umax = 0.0f, gssel = 0.0f, imax = 0.0f, ineg = 0.0f;
        int g = act ? (__ffs(act) - 1) : -1;
#pragma unroll
        for (int l = 0; l < NL; ++l) {
            float gl = sigmoidf_(fdec(d_gmax[b][l]));
            umax = fmaxf(umax, gl);
            if (l == g) gssel = gl;
            else        imax  = fmaxf(imax, gl);
            if (an & (1 << l)) ineg = fmaxf(ineg, gl);
        }

        float loss;
        if (g < 0) {
            loss = 0.5f * rankl(thres, umax) + 0.5f * rankl(thres, ineg);
        } else {
            loss = rankl(gssel, thres);
            if (imax > 0.0f) loss += 0.5f * rankl(thres, imax);
            loss += 0.5f * ((ineg > 0.0f) ? rankl(thres, ineg)
                                          : rankl(thres, imax));
        }
        d_loss[b] = loss;
    }
}

// ---------------------------------------------------------------------------
// Fused flat scan + inline per-row finalization + last-block reduction.
// ---------------------------------------------------------------------------
__global__ void __launch_bounds__(BDIM, 6)
scan_kernel(const float* __restrict__ x,
            const int*   __restrict__ y,
            const int*   __restrict__ yn,
            float*       __restrict__ out) {
    const int tid = threadIdx.x;
    const int c0 = blockIdx.x * SPAN;
    const int c1 = (c0 + SPAN < TOTCH) ? c0 + SPAN : TOTCH;

    __shared__ unsigned s_g[3][NL];
    __shared__ int      s_final[3];
    __shared__ int      s_last;
    if (tid < 3 * NL) s_g[tid / NL][tid % NL] = 0u;
    if (tid < 3) s_final[tid] = -1;
    __syncthreads();

    const int r0 = (c0 < TOTCH) ? ((c0 << 2) / NC) : NB;
    const float4* x4 = (const float4*)x;
    const int4*   y4 = (const int4*)y;
    const int4*   n4 = (const int4*)yn;

    auto proc = [&](int i, const float4& v, const int4& yq, const int4& nq) {
        const int q   = i << 2;
        const int row = q / NC;
        const int cls = q - row * NC;
        const int ro  = row - r0;
        if (cls <= NC - 4) {
            const unsigned h = (unsigned)cls & 3u;
            const unsigned tw = __ldg((const unsigned*)(d_tabs[h]) + ((cls - (int)h) >> 2));
            if (fmaxf(fmaxf(v.x, v.y), fmaxf(v.z, v.w)) > T1) {
                if (v.x > T1) { int p = atomicAdd(&d_ccnt[row], 1); if (p < CCAP) d_cand[row][p] = v.x; }
                if (v.y > T1) { int p = atomicAdd(&d_ccnt[row], 1); if (p < CCAP) d_cand[row][p] = v.y; }
                if (v.z > T1) { int p = atomicAdd(&d_ccnt[row], 1); if (p < CCAP) d_cand[row][p] = v.z; }
                if (v.w > T1) { int p = atomicAdd(&d_ccnt[row], 1); if (p < CCAP) d_cand[row][p] = v.w; }
            }
            if (tw != 0xFFFFFFFFu) {
                unsigned t0b =  tw        & 0xFF;
                unsigned t1b = (tw >> 8)  & 0xFF;
                unsigned t2b = (tw >> 16) & 0xFF;
                unsigned t3b = (tw >> 24) & 0xFF;
                if (t0b != 0xFF) atomicMax(&s_g[ro][t0b], fenc(v.x));
                if (t1b != 0xFF) atomicMax(&s_g[ro][t1b], fenc(v.y));
                if (t2b != 0xFF) atomicMax(&s_g[ro][t2b], fenc(v.z));
                if (t3b != 0xFF) atomicMax(&s_g[ro][t3b], fenc(v.w));
            }
            if (yq.x | yq.y | yq.z | yq.w) {
                if (yq.x) { unsigned t = tw & 0xFF;         if (t != 0xFF) atomicOr(&d_actg[row], 1 << t); }
                if (yq.y) { unsigned t = (tw >> 8) & 0xFF;  if (t != 0xFF) atomicOr(&d_actg[row], 1 << t); }
                if (yq.z) { unsigned t = (tw >> 16) & 0xFF; if (t != 0xFF) atomicOr(&d_actg[row], 1 << t); }
                if (yq.w) { unsigned t = (tw >> 24) & 0xFF; if (t != 0xFF) atomicOr(&d_actg[row], 1 << t); }
            }
            if (nq.x | nq.y | nq.z | nq.w) {
                if (nq.x) { unsigned t = tw & 0xFF;         if (t != 0xFF) atomicOr(&d_ang[row], 1 << t); }
                if (nq.y) { unsigned t = (tw >> 8) & 0xFF;  if (t != 0xFF) atomicOr(&d_ang[row], 1 << t); }
                if (nq.z) { unsigned t = (tw >> 16) & 0xFF; if (t != 0xFF) atomicOr(&d_ang[row], 1 << t); }
                if (nq.w) { unsigned t = (tw >> 24) & 0xFF; if (t != 0xFF) atomicOr(&d_ang[row], 1 << t); }
            }
        } else {
            // boundary chunk straddling a row edge (rare)
#pragma unroll
            for (int u = 0; u < 4; ++u) {
                float v1  = (u == 0) ? v.x : (u == 1) ? v.y : (u == 2) ? v.z : v.w;
                int   yv1 = (u == 0) ? yq.x : (u == 1) ? yq.y : (u == 2) ? yq.z : yq.w;
                int   nv1 = (u == 0) ? nq.x : (u == 1) ? nq.y : (u == 2) ? nq.z : nq.w;
                int qk = q + u;
                int rk = qk / NC;
                int ck = qk - rk * NC;
                if (v1 > T1) { int p = atomicAdd(&d_ccnt[rk], 1); if (p < CCAP) d_cand[rk][p] = v1; }
                unsigned t = __ldg(&d_tabs[0][ck]);
                if (t != 0xFF) {
                    int rok = rk - r0;
                    if (rok >= 0 && rok < 3) atomicMax(&s_g[rok][t], fenc(v1));
                    else                     atomicMax(&d_gmax[rk][t], fenc(v1));
                    if (yv1) atomicOr(&d_actg[rk], 1 << t);
                    if (nv1) atomicOr(&d_ang[rk],  1 << t);
                }
            }
        }
    };

    int i = c0 + tid;
    for (; i + BDIM < c1; i += 2 * BDIM) {
        float4 a0 = __ldcs(x4 + i);
        float4 a1 = __ldcs(x4 + i + BDIM);
        int4   b0 = __ldcs(y4 + i);
        int4   b1 = __ldcs(y4 + i + BDIM);
        int4   e0 = __ldcs(n4 + i);
        int4   e1 = __ldcs(n4 + i + BDIM);
        proc(i, a0, b0, e0);
        proc(i + BDIM, a1, b1, e1);
    }
    for (; i < c1; i += BDIM) {
        float4 a = __ldcs(x4 + i);
        int4   b = __ldcs(y4 + i);
        int4   e = __ldcs(n4 + i);
        proc(i, a, b, e);
    }

    __syncthreads();
    // flush smem group maxima to global
    if (tid < 3 * NL) {
        int ro = tid / NL, l = tid % NL;
        int row = r0 + ro;
        unsigned v = s_g[ro][l];
        if (v && row < NB) atomicMax(&d_gmax[row][l], v);
    }
    __syncthreads();
    __threadfence();   // publish candidates/gmax/activity before rowdone

    // per-row completion: covering rows of this span are [r_first, r_last]
    if (tid < 3 && c0 < TOTCH) {
        int r_first = (c0 << 2) / NC;
        int r_last  = ((c1 << 2) - 1) / NC;
        int r = r_first + tid;
        if (r <= r_last && r < NB) {
            int prev = atomicAdd(&d_rowdone[r], 1);
            if (prev == nblk_row(r) - 1) s_final[tid] = r;  // we complete row r
        }
    }
    __syncthreads();

    // warp w finalizes s_final[w] (if any)
    {
        const int w    = tid >> 5;
        const int lane = tid & 31;
        if (w < 3) {
            int r = s_final[w];
            if (r >= 0) {
                __threadfence();     // acquire side of the publish
                finalize_row(r, x, lane);
            }
        }
    }

    __syncthreads();
    if (tid == 0) {
        __threadfence();
        int done = atomicAdd(&d_done2, 1);
        s_last = (done == GRIDM - 1);
    }
    __syncthreads();
    if (s_last) {
        __threadfence();
        __shared__ float sh[BDIM];
        float s = 0.0f;
#pragma unroll
        for (int k = 0; k < NB / BDIM; ++k)
            s += d_loss[tid + k * BDIM];
        sh[tid] = s;
        __syncthreads();
        for (int o = BDIM / 2; o > 0; o >>= 1) {
            if (tid < o) sh[tid] += sh[tid + o];
            __syncthreads();
        }
        if (tid == 0) out[0] = sh[0];
    }
}

extern "C" void kernel_launch(void* const* d_in, const int* in_sizes, int n_in,
                              void* d_out, int out_size) {
    const float* x    = (const float*)d_in[0];
    const int*   y    = (const int*)d_in[1];
    const int*   yn   = (const int*)d_in[2];
    const void*  mask = (const void*)d_in[3];
    float*       out  = (float*)d_out;

    initdetect_kernel<<<256, 256>>>((const unsigned char*)mask);
    build_kernel<<<592, 256>>>(mask);
    scan_kernel<<<GRIDM, BDIM>>>(x, y, yn, out);
}

// round 14
// speedup vs baseline: 1.2654x; 1.2654x over previous
#include <cuda_runtime.h>
#include <math.h>
#include <stdint.h>
#include <float.h>

#define NB    2048
#define NC    9605
#define NL    20
#define NCP   9616                    // NC rounded up to 16
#define BDIM  256
#define CCAP  768                     // per-row candidate capacity
#define T1    2.5f                    // ~60 candidates expected for N(0,1)
#define TOTCH ((NB * NC) / 4)         // int4 chunks (exact: NB*NC % 4 == 0)
#define GRIDM 4736
#define SPAN  ((TOTCH + GRIDM - 1) / GRIDM)

// Scratch (no allocations allowed)
__device__ __align__(16) unsigned char d_tabs[4][NCP]; // shifted class->group
__device__ int      d_hist[4];
__device__ int      d_actg[NB];       // per-row group-activity bitmask (y)
__device__ int      d_ang[NB];        // per-row group-activity bitmask (y_neg)
__device__ unsigned d_gmax[NB][NL];   // per-row fenc'd group maxima
__device__ int      d_ccnt[NB];       // per-row candidate counts
__device__ float    d_cand[NB][CCAP]; // per-row candidate values
__device__ float    d_loss[NB];
__device__ int      d_done2;

// ---------------------------------------------------------------------------
// init + dtype detection fused
// ---------------------------------------------------------------------------
__global__ void __launch_bounds__(256)
initdetect_kernel(const unsigned char* __restrict__ raw) {
    int t0 = blockIdx.x * blockDim.x + threadIdx.x;
    int gs = gridDim.x * blockDim.x;
    if (t0 == 0) {
        d_done2 = 0;
        d_hist[0] = d_hist[1] = d_hist[2] = d_hist[3] = 0;
    }
    for (int i = t0; i < NB; i += gs) { d_actg[i] = 0; d_ang[i] = 0; d_ccnt[i] = 0; }
    for (int i = t0; i < NB * NL; i += gs) ((unsigned*)d_gmax)[i] = 0u;
    {
        uint4* p = (uint4*)d_tabs;
        const uint4 ff = make_uint4(0xFFFFFFFFu, 0xFFFFFFFFu,
                                    0xFFFFFFFFu, 0xFFFFFFFFu);
        for (int i = t0; i < (4 * NCP) / 16; i += gs) p[i] = ff;
    }
    // detect: flag nonzero bytes by (offset mod 4) over first NL*NC bytes
    const int total = NL * NC;
    const uint4* r4 = (const uint4*)raw;
    int f0 = 0, f1 = 0, f2 = 0, f3 = 0;
    int nv = total >> 4;
    for (int i = t0; i < nv; i += gs) {
        uint4 w = __ldg(r4 + i);
        unsigned a = w.x | w.y | w.z | w.w;
        f0 |= (a & 0x000000FFu) != 0;
        f1 |= (a & 0x0000FF00u) != 0;
        f2 |= (a & 0x00FF0000u) != 0;
        f3 |= (a & 0xFF000000u) != 0;
    }
    if (blockIdx.x == 0) {
        for (int i = (nv << 4) + threadIdx.x; i < total; i += blockDim.x)
            if (raw[i]) { int m = i & 3;
                f0 |= (m == 0); f1 |= (m == 1); f2 |= (m == 2); f3 |= (m == 3); }
    }
    if (f0) atomicOr(&d_hist[0], 1);
    if (f1) atomicOr(&d_hist[1], 1);
    if (f2) atomicOr(&d_hist[2], 1);
    if (f3) atomicOr(&d_hist[3], 1);
}

__device__ __forceinline__ void tab_set(int c, unsigned char g) {
#pragma unroll
    for (int h = 0; h < 4; ++h)
        if (c >= h) d_tabs[h][c - h] = g;
}

__global__ void __launch_bounds__(256)
build_kernel(const void* __restrict__ maskv) {
    int h0 = d_hist[0], h1 = d_hist[1], h2 = d_hist[2], h3 = d_hist[3];
    int mode;  // 0 = uint8, 1 = int32, 2 = float32
    if (h0 && !h1 && !h2 && !h3)        mode = 1;
    else if (!h0 && !h1 && (h2 || h3))  mode = 2;
    else                                 mode = 0;

    const int total = NL * NC;
    const int gs = gridDim.x * blockDim.x;
    const int t0 = blockIdx.x * blockDim.x + threadIdx.x;

    if (mode != 0) {
        const int4* m4 = (const int4*)maskv;  // int32/float32: !=0 bit test
        int nv = total >> 2;
        for (int i = t0; i < nv; i += gs) {
            int4 w = __ldg(m4 + i);
            int base = i << 2;
#pragma unroll
            for (int u = 0; u < 4; ++u) {
                int bits = (u == 0) ? w.x : (u == 1) ? w.y : (u == 2) ? w.z : w.w;
                if (bits != 0) {
                    int idx = base + u;
                    tab_set(idx % NC, (unsigned char)(idx / NC));
                }
            }
        }
        for (int idx = (nv << 2) + t0; idx < total; idx += gs)
            if (((const int*)maskv)[idx] != 0)
                tab_set(idx % NC, (unsigned char)(idx / NC));
    } else {
        const unsigned char* m8 = (const unsigned char*)maskv;
        for (int idx = t0; idx < total; idx += gs)
            if (m8[idx])
                tab_set(idx % NC, (unsigned char)(idx / NC));
    }
}

__device__ __forceinline__ float sigmoidf_(float v) {
    return 1.0f / (1.0f + expf(-v));
}
__device__ __forceinline__ float rankl(float x1, float x2) {
    float d = x2 - x1 + 0.05f;
    float s = 1.0f / (1.0f + expf(-10.0f * d));
    return (d > 0.0f) ? 2.0f * s : s;
}
__device__ __forceinline__ unsigned fenc(float v) {
    unsigned u = __float_as_uint(v);
    return (u & 0x80000000u) ? ~u : (u | 0x80000000u);
}
__device__ __forceinline__ float fdec(unsigned u) {
    return (u & 0x80000000u) ? __uint_as_float(u ^ 0x80000000u)
                             : __uint_as_float(~u);
}

// ---------------------------------------------------------------------------
// Fused flat scan (identical to the 72%-DRAM version)
// ---------------------------------------------------------------------------
__global__ void __launch_bounds__(BDIM, 6)
scan_kernel(const float* __restrict__ x,
            const int*   __restrict__ y,
            const int*   __restrict__ yn) {
    const int tid = threadIdx.x;
    const int c0 = blockIdx.x * SPAN;
    const int c1 = (c0 + SPAN < TOTCH) ? c0 + SPAN : TOTCH;

    __shared__ unsigned s_g[3][NL];
    if (tid < 3 * NL) s_g[tid / NL][tid % NL] = 0u;
    __syncthreads();

    const int r0 = (c0 < TOTCH) ? ((c0 << 2) / NC) : NB;
    const float4* x4 = (const float4*)x;
    const int4*   y4 = (const int4*)y;
    const int4*   n4 = (const int4*)yn;

    auto proc = [&](int i, const float4& v, const int4& yq, const int4& nq) {
        const int q   = i << 2;
        const int row = q / NC;
        const int cls = q - row * NC;
        const int ro  = row - r0;
        if (cls <= NC - 4) {
            const unsigned h = (unsigned)cls & 3u;
            const unsigned tw = __ldg((const unsigned*)(d_tabs[h]) + ((cls - (int)h) >> 2));
            if (fmaxf(fmaxf(v.x, v.y), fmaxf(v.z, v.w)) > T1) {
                if (v.x > T1) { int p = atomicAdd(&d_ccnt[row], 1); if (p < CCAP) d_cand[row][p] = v.x; }
                if (v.y > T1) { int p = atomicAdd(&d_ccnt[row], 1); if (p < CCAP) d_cand[row][p] = v.y; }
                if (v.z > T1) { int p = atomicAdd(&d_ccnt[row], 1); if (p < CCAP) d_cand[row][p] = v.z; }
                if (v.w > T1) { int p = atomicAdd(&d_ccnt[row], 1); if (p < CCAP) d_cand[row][p] = v.w; }
            }
            if (tw != 0xFFFFFFFFu) {
                unsigned t0b =  tw        & 0xFF;
                unsigned t1b = (tw >> 8)  & 0xFF;
                unsigned t2b = (tw >> 16) & 0xFF;
                unsigned t3b = (tw >> 24) & 0xFF;
                if (t0b != 0xFF) atomicMax(&s_g[ro][t0b], fenc(v.x));
                if (t1b != 0xFF) atomicMax(&s_g[ro][t1b], fenc(v.y));
                if (t2b != 0xFF) atomicMax(&s_g[ro][t2b], fenc(v.z));
                if (t3b != 0xFF) atomicMax(&s_g[ro][t3b], fenc(v.w));
            }
            if (yq.x | yq.y | yq.z | yq.w) {
                if (yq.x) { unsigned t = tw & 0xFF;         if (t != 0xFF) atomicOr(&d_actg[row], 1 << t); }
                if (yq.y) { unsigned t = (tw >> 8) & 0xFF;  if (t != 0xFF) atomicOr(&d_actg[row], 1 << t); }
                if (yq.z) { unsigned t = (tw >> 16) & 0xFF; if (t != 0xFF) atomicOr(&d_actg[row], 1 << t); }
                if (yq.w) { unsigned t = (tw >> 24) & 0xFF; if (t != 0xFF) atomicOr(&d_actg[row], 1 << t); }
            }
            if (nq.x | nq.y | nq.z | nq.w) {
                if (nq.x) { unsigned t = tw & 0xFF;         if (t != 0xFF) atomicOr(&d_ang[row], 1 << t); }
                if (nq.y) { unsigned t = (tw >> 8) & 0xFF;  if (t != 0xFF) atomicOr(&d_ang[row], 1 << t); }
                if (nq.z) { unsigned t = (tw >> 16) & 0xFF; if (t != 0xFF) atomicOr(&d_ang[row], 1 << t); }
                if (nq.w) { unsigned t = (tw >> 24) & 0xFF; if (t != 0xFF) atomicOr(&d_ang[row], 1 << t); }
            }
        } else {
            // boundary chunk straddling a row edge (rare)
#pragma unroll
            for (int u = 0; u < 4; ++u) {
                float v1  = (u == 0) ? v.x : (u == 1) ? v.y : (u == 2) ? v.z : v.w;
                int   yv1 = (u == 0) ? yq.x : (u == 1) ? yq.y : (u == 2) ? yq.z : yq.w;
                int   nv1 = (u == 0) ? nq.x : (u == 1) ? nq.y : (u == 2) ? nq.z : nq.w;
                int qk = q + u;
                int rk = qk / NC;
                int ck = qk - rk * NC;
                if (v1 > T1) { int p = atomicAdd(&d_ccnt[rk], 1); if (p < CCAP) d_cand[rk][p] = v1; }
                unsigned t = __ldg(&d_tabs[0][ck]);
                if (t != 0xFF) {
                    int rok = rk - r0;
                    if (rok >= 0 && rok < 3) atomicMax(&s_g[rok][t], fenc(v1));
                    else                     atomicMax(&d_gmax[rk][t], fenc(v1));
                    if (yv1) atomicOr(&d_actg[rk], 1 << t);
                    if (nv1) atomicOr(&d_ang[rk],  1 << t);
                }
            }
        }
    };

    int i = c0 + tid;
    for (; i + BDIM < c1; i += 2 * BDIM) {
        float4 a0 = __ldcs(x4 + i);
        float4 a1 = __ldcs(x4 + i + BDIM);
        int4   b0 = __ldcs(y4 + i);
        int4   b1 = __ldcs(y4 + i + BDIM);
        int4   e0 = __ldcs(n4 + i);
        int4   e1 = __ldcs(n4 + i + BDIM);
        proc(i, a0, b0, e0);
        proc(i + BDIM, a1, b1, e1);
    }
    for (; i < c1; i += BDIM) {
        float4 a = __ldcs(x4 + i);
        int4   b = __ldcs(y4 + i);
        int4   e = __ldcs(n4 + i);
        proc(i, a, b, e);
    }

    __syncthreads();
    if (tid < 3 * NL) {
        int ro = tid / NL, l = tid % NL;
        int row = r0 + ro;
        unsigned v = s_g[ro][l];
        if (v && row < NB) atomicMax(&d_gmax[row][l], v);
    }
}

// ---------------------------------------------------------------------------
// Phase 2: warp per row, with the serial tail parallelized across lanes.
// ---------------------------------------------------------------------------
__global__ void __launch_bounds__(BDIM)
loss_kernel(const float* __restrict__ x, float* __restrict__ out) {
    const int tid  = threadIdx.x;
    const int w    = tid >> 5;
    const int lane = tid & 31;
    const int b    = blockIdx.x * 8 + w;

    __shared__ int s_last;

    {
        // issue per-group max + activity loads immediately (overlap latency)
        unsigned genc = (lane < NL) ? __ldg(&d_gmax[b][lane]) : 0u;
        int act_l = (lane == 0) ? __ldg(&d_actg[b]) : 0;
        int an_l  = (lane == 0) ? __ldg(&d_ang[b])  : 0;

        int cnt = __ldg(&d_ccnt[b]);
        const float* xr = x + (size_t)b * NC;

        if (cnt < 11 || cnt > CCAP) {
            // bisection fallback (unreachable for the bench distribution)
            float tlo = -3.0e38f, thi = 3.0e38f, thr = T1;
            for (int it = 0; it < 120; ++it) {
                int local = 0;
                for (int c = lane; c < NC; c += 32) local += (__ldg(xr + c) > thr);
#pragma unroll
                for (int o = 16; o > 0; o >>= 1)
                    local += __shfl_down_sync(0xffffffffu, local, o);
                int c2 = __shfl_sync(0xffffffffu, local, 0);
                if (c2 > 128)     { tlo = thr; }
                else if (c2 < 11) { thi = thr; }
                else break;
                thr = 0.5f * (tlo + thi);
            }
            if (lane == 0) d_ccnt[b] = 0;
            __syncwarp();
            for (int c = lane; c < NC; c += 32) {
                float v = __ldg(xr + c);
                if (v > thr) {
                    int p = atomicAdd(&d_ccnt[b], 1);
                    if (p < CCAP) d_cand[b][p] = v;
                }
            }
            __syncwarp();
            cnt = d_ccnt[b];
            if (cnt > CCAP) cnt = CCAP;
        }

        float v11;
        if (cnt <= 128) {
            float v0 = (lane      < cnt) ? __ldg(&d_cand[b][lane])      : -FLT_MAX;
            float v1 = (lane + 32 < cnt) ? __ldg(&d_cand[b][lane + 32]) : -FLT_MAX;
            float v2 = (lane + 64 < cnt) ? __ldg(&d_cand[b][lane + 64]) : -FLT_MAX;
            float v3 = (lane + 96 < cnt) ? __ldg(&d_cand[b][lane + 96]) : -FLT_MAX;
            v11 = -FLT_MAX;
#pragma unroll
            for (int r = 0; r < 11; ++r) {
                float lm = fmaxf(fmaxf(v0, v1), fmaxf(v2, v3));
                float m = lm;
#pragma unroll
                for (int o = 16; o > 0; o >>= 1)
                    m = fmaxf(m, __shfl_xor_sync(0xffffffffu, m, o));
                if (r == 10) { v11 = m; break; }
                unsigned ballot = __ballot_sync(0xffffffffu, lm == m);
                int owner = __ffs(ballot) - 1;
                if (lane == owner) {
                    if      (v0 == m) v0 = -FLT_MAX;
                    else if (v1 == m) v1 = -FLT_MAX;
                    else if (v2 == m) v2 = -FLT_MAX;
                    else              v3 = -FLT_MAX;
                }
            }
        } else {
            float found = -FLT_MAX;
            for (int i2 = lane; i2 < cnt; i2 += 32) {
                float vi = d_cand[b][i2];
                int rank = 0;
                for (int j = 0; j < cnt; ++j) {
                    float vj = d_cand[b][j];
                    rank += (vj > vi) || (vj == vi && j < i2);
                }
                if (rank == 10) found = vi;
            }
#pragma unroll
            for (int o = 16; o > 0; o >>= 1)
                found = fmaxf(found, __shfl_xor_sync(0xffffffffu, found, o));
            v11 = found;
        }

        // parallel per-group sigmoid + warp reductions
        const int act = __shfl_sync(0xffffffffu, act_l, 0);
        const int an  = __shfl_sync(0xffffffffu, an_l,  0);
        const int g   = act ? (__ffs(act) - 1) : -1;

        float gl = (lane < NL) ? sigmoidf_(fdec(genc)) : 0.0f;
        float um = gl;                                   // union max
        float im = (lane != g) ? gl : 0.0f;              // incorrect max
        float in = (an & (1 << lane)) ? gl : 0.0f;       // neg-active max
#pragma unroll
        for (int o = 16; o > 0; o >>= 1) {
            um = fmaxf(um, __shfl_xor_sync(0xffffffffu, um, o));
            im = fmaxf(im, __shfl_xor_sync(0xffffffffu, im, o));
            in = fmaxf(in, __shfl_xor_sync(0xffffffffu, in, o));
        }
        float gssel = (g >= 0) ? __shfl_sync(0xffffffffu, gl, g) : 0.0f;

        if (lane == 0) {
            const float thres = fmaxf(sigmoidf_(v11), 0.5f);
            float loss;
            if (g < 0) {
                loss = 0.5f * rankl(thres, um) + 0.5f * rankl(thres, in);
            } else {
                loss = rankl(gssel, thres);
                if (im > 0.0f) loss += 0.5f * rankl(thres, im);
                loss += 0.5f * ((in > 0.0f) ? rankl(thres, in)
                                            : rankl(thres, im));
            }
            d_loss[b] = loss;
        }
    }

    __syncthreads();
    if (tid == 0) {
        __threadfence();
        int done = atomicAdd(&d_done2, 1);
        s_last = (done == NB / 8 - 1);
    }
    __syncthreads();
    if (s_last) {
        __shared__ float sh[BDIM];
        float s = 0.0f;
#pragma unroll
        for (int k = 0; k < NB / BDIM; ++k)
            s += d_loss[tid + k * BDIM];
        sh[tid] = s;
        __syncthreads();
        for (int o = BDIM / 2; o > 0; o >>= 1) {
            if (tid < o) sh[tid] += sh[tid + o];
            __syncthreads();
        }
        if (tid == 0) out[0] = sh[0];
    }
}

extern "C" void kernel_launch(void* const* d_in, const int* in_sizes, int n_in,
                              void* d_out, int out_size) {
    const float* x    = (const float*)d_in[0];
    const int*   y    = (const int*)d_in[1];
    const int*   yn   = (const int*)d_in[2];
    const void*  mask = (const void*)d_in[3];
    float*       out  = (float*)d_out;

    initdetect_kernel<<<256, 256>>>((const unsigned char*)mask);
    build_kernel<<<592, 256>>>(mask);
    scan_kernel<<<GRIDM, BDIM>>>(x, y, yn);
    loss_kernel<<<NB / 8, BDIM>>>(x, out);
}

// round 16
// speedup vs baseline: 1.2661x; 1.0005x over previous
#include <cuda_runtime.h>
#include <math.h>
#include <stdint.h>
#include <float.h>

#define NB    2048
#define NC    9605
#define NL    20
#define NCP   9616                    // NC rounded up to 16
#define BDIM  256
#define CCAP  768                     // per-row candidate capacity
#define T1    2.5f                    // ~60 candidates expected for N(0,1)
#define TOTCH ((NB * NC) / 4)         // int4 chunks (exact: NB*NC % 4 == 0)
#define GRIDM 4440                    // 148 SMs x 6 resident x 5 exact waves
#define SPAN  ((TOTCH + GRIDM - 1) / GRIDM)   // 1108 chunks -> <=2 rows/block

// Scratch (no allocations allowed). Zero at module load; loss_kernel resets
// everything it consumed, so graph replays see identical initial state.
__device__ __align__(16) unsigned char d_tabs[4][NCP]; // shifted class->group
__device__ int      d_hist[4];        // OR-idempotent across replays
__device__ int      d_actg[NB];       // per-row group-activity bitmask (y)
__device__ int      d_ang[NB];        // per-row group-activity bitmask (y_neg)
__device__ unsigned d_gmax[NB][NL];   // per-row fenc'd group maxima
__device__ int      d_ccnt[NB];       // per-row candidate counts
__device__ float    d_cand[NB][CCAP]; // per-row candidate values
__device__ float    d_loss[NB];
__device__ int      d_done2;

// ---------------------------------------------------------------------------
// detect mask dtype + fill shifted tables with 0xFF (both idempotent)
// ---------------------------------------------------------------------------
__global__ void __launch_bounds__(256)
initdetect_kernel(const unsigned char* __restrict__ raw) {
    int t0 = blockIdx.x * blockDim.x + threadIdx.x;
    int gs = gridDim.x * blockDim.x;
    {
        uint4* p = (uint4*)d_tabs;
        const uint4 ff = make_uint4(0xFFFFFFFFu, 0xFFFFFFFFu,
                                    0xFFFFFFFFu, 0xFFFFFFFFu);
        for (int i = t0; i < (4 * NCP) / 16; i += gs) p[i] = ff;
    }
    // detect: flag nonzero bytes by (offset mod 4) over first NL*NC bytes
    const int total = NL * NC;
    const uint4* r4 = (const uint4*)raw;
    int f0 = 0, f1 = 0, f2 = 0, f3 = 0;
    int nv = total >> 4;
    for (int i = t0; i < nv; i += gs) {
        uint4 w = __ldg(r4 + i);
        unsigned a = w.x | w.y | w.z | w.w;
        f0 |= (a & 0x000000FFu) != 0;
        f1 |= (a & 0x0000FF00u) != 0;
        f2 |= (a & 0x00FF0000u) != 0;
        f3 |= (a & 0xFF000000u) != 0;
    }
    if (blockIdx.x == 0) {
        for (int i = (nv << 4) + threadIdx.x; i < total; i += blockDim.x)
            if (raw[i]) { int m = i & 3;
                f0 |= (m == 0); f1 |= (m == 1); f2 |= (m == 2); f3 |= (m == 3); }
    }
    if (f0) atomicOr(&d_hist[0], 1);
    if (f1) atomicOr(&d_hist[1], 1);
    if (f2) atomicOr(&d_hist[2], 1);
    if (f3) atomicOr(&d_hist[3], 1);
}

__device__ __forceinline__ void tab_set(int c, unsigned char g) {
#pragma unroll
    for (int h = 0; h < 4; ++h)
        if (c >= h) d_tabs[h][c - h] = g;
}

__global__ void __launch_bounds__(256)
build_kernel(const void* __restrict__ maskv) {
    int h0 = d_hist[0], h1 = d_hist[1], h2 = d_hist[2], h3 = d_hist[3];
    int mode;  // 0 = uint8, 1 = int32, 2 = float32
    if (h0 && !h1 && !h2 && !h3)        mode = 1;
    else if (!h0 && !h1 && (h2 || h3))  mode = 2;
    else                                 mode = 0;

    const int total = NL * NC;
    const int gs = gridDim.x * blockDim.x;
    const int t0 = blockIdx.x * blockDim.x + threadIdx.x;

    if (mode != 0) {
        const int4* m4 = (const int4*)maskv;  // int32/float32: !=0 bit test
        int nv = total >> 2;
        for (int i = t0; i < nv; i += gs) {
            int4 w = __ldg(m4 + i);
            int base = i << 2;
#pragma unroll
            for (int u = 0; u < 4; ++u) {
                int bits = (u == 0) ? w.x : (u == 1) ? w.y : (u == 2) ? w.z : w.w;
                if (bits != 0) {
                    int idx = base + u;
                    tab_set(idx % NC, (unsigned char)(idx / NC));
                }
            }
        }
        for (int idx = (nv << 2) + t0; idx < total; idx += gs)
            if (((const int*)maskv)[idx] != 0)
                tab_set(idx % NC, (unsigned char)(idx / NC));
    } else {
        const unsigned char* m8 = (const unsigned char*)maskv;
        for (int idx = t0; idx < total; idx += gs)
            if (m8[idx])
                tab_set(idx % NC, (unsigned char)(idx / NC));
    }
}

__device__ __forceinline__ float sigmoidf_(float v) {
    return 1.0f / (1.0f + expf(-v));
}
__device__ __forceinline__ float rankl(float x1, float x2) {
    float d = x2 - x1 + 0.05f;
    float s = 1.0f / (1.0f + expf(-10.0f * d));
    return (d > 0.0f) ? 2.0f * s : s;
}
__device__ __forceinline__ unsigned fenc(float v) {
    unsigned u = __float_as_uint(v);
    return (u & 0x80000000u) ? ~u : (u | 0x80000000u);
}
__device__ __forceinline__ float fdec(unsigned u) {
    return (u & 0x80000000u) ? __uint_as_float(u ^ 0x80000000u)
                             : __uint_as_float(~u);
}

// ---------------------------------------------------------------------------
// Fused flat scan (identical hot loop to the 72%-DRAM version)
// ---------------------------------------------------------------------------
__global__ void __launch_bounds__(BDIM, 6)
scan_kernel(const float* __restrict__ x,
            const int*   __restrict__ y,
            const int*   __restrict__ yn) {
    const int tid = threadIdx.x;
    const int c0 = blockIdx.x * SPAN;
    const int c1 = (c0 + SPAN < TOTCH) ? c0 + SPAN : TOTCH;

    __shared__ unsigned s_g[3][NL];
    if (tid < 3 * NL) s_g[tid / NL][tid % NL] = 0u;
    __syncthreads();

    const int r0 = (c0 < TOTCH) ? ((c0 << 2) / NC) : NB;
    const float4* x4 = (const float4*)x;
    const int4*   y4 = (const int4*)y;
    const int4*   n4 = (const int4*)yn;

    auto proc = [&](int i, const float4& v, const int4& yq, const int4& nq) {
        const int q   = i << 2;
        const int row = q / NC;
        const int cls = q - row * NC;
        const int ro  = row - r0;
        if (cls <= NC - 4) {
            const unsigned h = (unsigned)cls & 3u;
            const unsigned tw = __ldg((const unsigned*)(d_tabs[h]) + ((cls - (int)h) >> 2));
            if (fmaxf(fmaxf(v.x, v.y), fmaxf(v.z, v.w)) > T1) {
                if (v.x > T1) { int p = atomicAdd(&d_ccnt[row], 1); if (p < CCAP) d_cand[row][p] = v.x; }
                if (v.y > T1) { int p = atomicAdd(&d_ccnt[row], 1); if (p < CCAP) d_cand[row][p] = v.y; }
                if (v.z > T1) { int p = atomicAdd(&d_ccnt[row], 1); if (p < CCAP) d_cand[row][p] = v.z; }
                if (v.w > T1) { int p = atomicAdd(&d_ccnt[row], 1); if (p < CCAP) d_cand[row][p] = v.w; }
            }
            if (tw != 0xFFFFFFFFu) {
                unsigned t0b =  tw        & 0xFF;
                unsigned t1b = (tw >> 8)  & 0xFF;
                unsigned t2b = (tw >> 16) & 0xFF;
                unsigned t3b = (tw >> 24) & 0xFF;
                if (t0b != 0xFF) atomicMax(&s_g[ro][t0b], fenc(v.x));
                if (t1b != 0xFF) atomicMax(&s_g[ro][t1b], fenc(v.y));
                if (t2b != 0xFF) atomicMax(&s_g[ro][t2b], fenc(v.z));
                if (t3b != 0xFF) atomicMax(&s_g[ro][t3b], fenc(v.w));
            }
            if (yq.x | yq.y | yq.z | yq.w) {
                if (yq.x) { unsigned t = tw & 0xFF;         if (t != 0xFF) atomicOr(&d_actg[row], 1 << t); }
                if (yq.y) { unsigned t = (tw >> 8) & 0xFF;  if (t != 0xFF) atomicOr(&d_actg[row], 1 << t); }
                if (yq.z) { unsigned t = (tw >> 16) & 0xFF; if (t != 0xFF) atomicOr(&d_actg[row], 1 << t); }
                if (yq.w) { unsigned t = (tw >> 24) & 0xFF; if (t != 0xFF) atomicOr(&d_actg[row], 1 << t); }
            }
            if (nq.x | nq.y | nq.z | nq.w) {
                if (nq.x) { unsigned t = tw & 0xFF;         if (t != 0xFF) atomicOr(&d_ang[row], 1 << t); }
                if (nq.y) { unsigned t = (tw >> 8) & 0xFF;  if (t != 0xFF) atomicOr(&d_ang[row], 1 << t); }
                if (nq.z) { unsigned t = (tw >> 16) & 0xFF; if (t != 0xFF) atomicOr(&d_ang[row], 1 << t); }
                if (nq.w) { unsigned t = (tw >> 24) & 0xFF; if (t != 0xFF) atomicOr(&d_ang[row], 1 << t); }
            }
        } else {
            // boundary chunk straddling a row edge (rare)
#pragma unroll
            for (int u = 0; u < 4; ++u) {
                float v1  = (u == 0) ? v.x : (u == 1) ? v.y : (u == 2) ? v.z : v.w;
                int   yv1 = (u == 0) ? yq.x : (u == 1) ? yq.y : (u == 2) ? yq.z : yq.w;
                int   nv1 = (u == 0) ? nq.x : (u == 1) ? nq.y : (u == 2) ? nq.z : nq.w;
                int qk = q + u;
                int rk = qk / NC;
                int ck = qk - rk * NC;
                if (v1 > T1) { int p = atomicAdd(&d_ccnt[rk], 1); if (p < CCAP) d_cand[rk][p] = v1; }
                unsigned t = __ldg(&d_tabs[0][ck]);
                if (t != 0xFF) {
                    int rok = rk - r0;
                    if (rok >= 0 && rok < 3) atomicMax(&s_g[rok][t], fenc(v1));
                    else                     atomicMax(&d_gmax[rk][t], fenc(v1));
                    if (yv1) atomicOr(&d_actg[rk], 1 << t);
                    if (nv1) atomicOr(&d_ang[rk],  1 << t);
                }
            }
        }
    };

    int i = c0 + tid;
    for (; i + BDIM < c1; i += 2 * BDIM) {
        float4 a0 = __ldcs(x4 + i);
        float4 a1 = __ldcs(x4 + i + BDIM);
        int4   b0 = __ldcs(y4 + i);
        int4   b1 = __ldcs(y4 + i + BDIM);
        int4   e0 = __ldcs(n4 + i);
        int4   e1 = __ldcs(n4 + i + BDIM);
        proc(i, a0, b0, e0);
        proc(i + BDIM, a1, b1, e1);
    }
    for (; i < c1; i += BDIM) {
        float4 a = __ldcs(x4 + i);
        int4   b = __ldcs(y4 + i);
        int4   e = __ldcs(n4 + i);
        proc(i, a, b, e);
    }

    __syncthreads();
    if (tid < 3 * NL) {
        int ro = tid / NL, l = tid % NL;
        int row = r0 + ro;
        unsigned v = s_g[ro][l];
        if (v && row < NB) atomicMax(&d_gmax[row][l], v);
    }
}

// ---------------------------------------------------------------------------
// Phase 2: warp per row, parallel tail + scratch self-reset for graph replay.
// ---------------------------------------------------------------------------
__global__ void __launch_bounds__(BDIM)
loss_kernel(const float* __restrict__ x, float* __restrict__ out) {
    const int tid  = threadIdx.x;
    const int w    = tid >> 5;
    const int lane = tid & 31;
    const int b    = blockIdx.x * 8 + w;

    __shared__ int s_last;

    {
        // issue per-group max + activity loads immediately (overlap latency)
        unsigned genc = (lane < NL) ? __ldg(&d_gmax[b][lane]) : 0u;
        int act_l = (lane == 0) ? __ldg(&d_actg[b]) : 0;
        int an_l  = (lane == 0) ? __ldg(&d_ang[b])  : 0;

        int cnt = __ldg(&d_ccnt[b]);
        const float* xr = x + (size_t)b * NC;

        if (cnt < 11 || cnt > CCAP) {
            // bisection fallback (unreachable for the bench distribution)
            float tlo = -3.0e38f, thi = 3.0e38f, thr = T1;
            for (int it = 0; it < 120; ++it) {
                int local = 0;
                for (int c = lane; c < NC; c += 32) local += (__ldg(xr + c) > thr);
#pragma unroll
                for (int o = 16; o > 0; o >>= 1)
                    local += __shfl_down_sync(0xffffffffu, local, o);
                int c2 = __shfl_sync(0xffffffffu, local, 0);
                if (c2 > 128)     { tlo = thr; }
                else if (c2 < 11) { thi = thr; }
                else break;
                thr = 0.5f * (tlo + thi);
            }
            if (lane == 0) d_ccnt[b] = 0;
            __syncwarp();
            for (int c = lane; c < NC; c += 32) {
                float v = __ldg(xr + c);
                if (v > thr) {
                    int p = atomicAdd(&d_ccnt[b], 1);
                    if (p < CCAP) d_cand[b][p] = v;
                }
            }
            __syncwarp();
            cnt = d_ccnt[b];
            if (cnt > CCAP) cnt = CCAP;
        }

        float v11;
        if (cnt <= 128) {
            float v0 = (lane      < cnt) ? __ldg(&d_cand[b][lane])      : -FLT_MAX;
            float v1 = (lane + 32 < cnt) ? __ldg(&d_cand[b][lane + 32]) : -FLT_MAX;
            float v2 = (lane + 64 < cnt) ? __ldg(&d_cand[b][lane + 64]) : -FLT_MAX;
            float v3 = (lane + 96 < cnt) ? __ldg(&d_cand[b][lane + 96]) : -FLT_MAX;
            v11 = -FLT_MAX;
#pragma unroll
            for (int r = 0; r < 11; ++r) {
                float lm = fmaxf(fmaxf(v0, v1), fmaxf(v2, v3));
                float m = lm;
#pragma unroll
                for (int o = 16; o > 0; o >>= 1)
                    m = fmaxf(m, __shfl_xor_sync(0xffffffffu, m, o));
                if (r == 10) { v11 = m; break; }
                unsigned ballot = __ballot_sync(0xffffffffu, lm == m);
                int owner = __ffs(ballot) - 1;
                if (lane == owner) {
                    if      (v0 == m) v0 = -FLT_MAX;
                    else if (v1 == m) v1 = -FLT_MAX;
                    else if (v2 == m) v2 = -FLT_MAX;
                    else              v3 = -FLT_MAX;
                }
            }
        } else {
            float found = -FLT_MAX;
            for (int i2 = lane; i2 < cnt; i2 += 32) {
                float vi = d_cand[b][i2];
                int rank = 0;
                for (int j = 0; j < cnt; ++j) {
                    float vj = d_cand[b][j];
                    rank += (vj > vi) || (vj == vi && j < i2);
                }
                if (rank == 10) found = vi;
            }
#pragma unroll
            for (int o = 16; o > 0; o >>= 1)
                found = fmaxf(found, __shfl_xor_sync(0xffffffffu, found, o));
            v11 = found;
        }

        // parallel per-group sigmoid + warp reductions
        const int act = __shfl_sync(0xffffffffu, act_l, 0);
        const int an  = __shfl_sync(0xffffffffu, an_l,  0);
        const int g   = act ? (__ffs(act) - 1) : -1;

        float gl = (lane < NL) ? sigmoidf_(fdec(genc)) : 0.0f;
        float um = gl;
        float im = (lane != g) ? gl : 0.0f;
        float in = (an & (1 << lane)) ? gl : 0.0f;
#pragma unroll
        for (int o = 16; o > 0; o >>= 1) {
            um = fmaxf(um, __shfl_xor_sync(0xffffffffu, um, o));
            im = fmaxf(im, __shfl_xor_sync(0xffffffffu, im, o));
            in = fmaxf(in, __shfl_xor_sync(0xffffffffu, in, o));
        }
        float gssel = (g >= 0) ? __shfl_sync(0xffffffffu, gl, g) : 0.0f;

        if (lane == 0) {
            const float thres = fmaxf(sigmoidf_(v11), 0.5f);
            float loss;
            if (g < 0) {
                loss = 0.5f * rankl(thres, um) + 0.5f * rankl(thres, in);
            } else {
                loss = rankl(gssel, thres);
                if (im > 0.0f) loss += 0.5f * rankl(thres, im);
                loss += 0.5f * ((in > 0.0f) ? rankl(thres, in)
                                            : rankl(thres, im));
            }
            d_loss[b] = loss;
        }

        // self-reset consumed scratch for the next graph replay
        if (lane < NL) d_gmax[b][lane] = 0u;
        if (lane == 0) { d_actg[b] = 0; d_ang[b] = 0; d_ccnt[b] = 0; }
    }

    __syncthreads();
    if (tid == 0) {
        __threadfence();
        int done = atomicAdd(&d_done2, 1);
        s_last = (done == NB / 8 - 1);
    }
    __syncthreads();
    if (s_last) {
        __shared__ float sh[BDIM];
        float s = 0.0f;
#pragma unroll
        for (int k = 0; k < NB / BDIM; ++k)
            s += d_loss[tid + k * BDIM];
        sh[tid] = s;
        __syncthreads();
        for (int o = BDIM / 2; o > 0; o >>= 1) {
            if (tid < o) sh[tid] += sh[tid + o];
            __syncthreads();
        }
        if (tid == 0) { out[0] = sh[0]; d_done2 = 0; }
    }
}

extern "C" void kernel_launch(void* const* d_in, const int* in_sizes, int n_in,
                              void* d_out, int out_size) {
    const float* x    = (const float*)d_in[0];
    const int*   y    = (const int*)d_in[1];
    const int*   yn   = (const int*)d_in[2];
    const void*  mask = (const void*)d_in[3];
    float*       out  = (float*)d_out;

    initdetect_kernel<<<592, 256>>>((const unsigned char*)mask);
    build_kernel<<<592, 256>>>(mask);
    scan_kernel<<<GRIDM, BDIM>>>(x, y, yn);
    loss_kernel<<<NB / 8, BDIM>>>(x, out);
}